// round 13
// baseline (speedup 1.0000x reference)
#include <cuda_runtime.h>
#include <cuda_bf16.h>
#include <cuda_fp16.h>
#include <cuda_fp8.h>
#include <math.h>
#include <stdint.h>

// Problem constants
#define NB 4
#define NT 2048
#define NC 1280
#define NH 10
#define ND 128
#define NF 5120
#define NBT (NB*NT)          // 8192
#define NC3 (3*NC)           // 3840
#define EPSF 1e-5f
#define ATT_SCALE 0.08838834764831845f   // 1/sqrt(128)

// ---------------------------------------------------------------------------
// Scratch (device globals)
// ---------------------------------------------------------------------------
__device__ __half g_xn_hi[(size_t)NBT * NC];       // rmsnorm1 out, fp16 hi
__device__ __half g_xn_lo[(size_t)NBT * NC];       // rmsnorm1 out, fp16 lo
__device__ __half g_xn16[(size_t)NBT * NC];        // rmsnorm2 out, fp16 single
__device__ float g_qkv[(size_t)NBT * NC3];
__device__ __half g_qb[(size_t)NB * NH * NT * ND];
__device__ __half g_kb[(size_t)NB * NH * NT * ND];
__device__ __half g_vb[(size_t)NB * NH * NT * ND];
__device__ __half g_ao[(size_t)NBT * NC];          // attention out, fp16 single
__device__ float g_y1 [(size_t)NBT * NC];
__device__ __half g_hb[(size_t)NBT * NF];          // fc1+srelu out, fp16 single
// transposed weights [N,K], fp16 single
__device__ __half g_wqkvT[(size_t)NC3 * NC];
__device__ __half g_woutT[(size_t)NC * NC];
__device__ __half g_wfc1T[(size_t)NF * NC];
__device__ __half g_wfc2T[(size_t)NC * NF];

// ---------------------------------------------------------------------------
// PTX helpers
// ---------------------------------------------------------------------------
__device__ __forceinline__ uint32_t smem_u32(const void* p) {
    uint32_t a;
    asm("{ .reg .u64 t; cvta.to.shared.u64 t, %1; cvt.u32.u64 %0, t; }" : "=r"(a) : "l"(p));
    return a;
}
__device__ __forceinline__ void cp16(uint32_t dst, const void* src) {
    asm volatile("cp.async.cg.shared.global [%0], [%1], 16;" :: "r"(dst), "l"(src));
}
__device__ __forceinline__ void ldsm_x4(uint32_t& r0, uint32_t& r1, uint32_t& r2,
                                        uint32_t& r3, uint32_t addr) {
    asm volatile("ldmatrix.sync.aligned.m8n8.x4.shared.b16 {%0,%1,%2,%3}, [%4];"
                 : "=r"(r0), "=r"(r1), "=r"(r2), "=r"(r3) : "r"(addr));
}
__device__ __forceinline__ void ldsm_x4t(uint32_t& r0, uint32_t& r1, uint32_t& r2,
                                         uint32_t& r3, uint32_t addr) {
    asm volatile("ldmatrix.sync.aligned.m8n8.x4.trans.shared.b16 {%0,%1,%2,%3}, [%4];"
                 : "=r"(r0), "=r"(r1), "=r"(r2), "=r"(r3) : "r"(addr));
}
__device__ __forceinline__ void mma16816h(float* c, const uint32_t* a,
                                          uint32_t b0, uint32_t b1) {
    asm volatile(
        "mma.sync.aligned.m16n8k16.row.col.f32.f16.f16.f32 "
        "{%0,%1,%2,%3}, {%4,%5,%6,%7}, {%8,%9}, {%0,%1,%2,%3};"
        : "+f"(c[0]), "+f"(c[1]), "+f"(c[2]), "+f"(c[3])
        : "r"(a[0]), "r"(a[1]), "r"(a[2]), "r"(a[3]), "r"(b0), "r"(b1));
}

// ---------------------------------------------------------------------------
// splits / packs
// ---------------------------------------------------------------------------
__device__ __forceinline__ void split_h16(float v, __half& h, __half& l) {
    h = __float2half_rn(v);
    l = __float2half_rn(v - __half2float(h));
}
__device__ __forceinline__ uint32_t pack_h2(float lo, float hi) {
    __half2 t = __floats2half2_rn(lo, hi);
    return *(uint32_t*)&t;
}

// ---------------------------------------------------------------------------
// RMSNorm variants
// ---------------------------------------------------------------------------
__device__ __forceinline__ float rms_row_scale(const float* p, int ncols, int tid) {
    float ss = 0.f;
    for (int c = tid; c < ncols; c += 256) { float v = p[c]; ss = fmaf(v, v, ss); }
    #pragma unroll
    for (int off = 16; off; off >>= 1) ss += __shfl_xor_sync(0xffffffffu, ss, off);
    __shared__ float red[8];
    int wid = tid >> 5, lane = tid & 31;
    if (lane == 0) red[wid] = ss;
    __syncthreads();
    float tot = 0.f;
    #pragma unroll
    for (int i = 0; i < 8; i++) tot += red[i];
    return rsqrtf(tot / (float)ncols + EPSF);
}

__global__ __launch_bounds__(256)
void rmsnorm_split_h(const float* __restrict__ in, const float* __restrict__ w,
                     __half* __restrict__ ohi, __half* __restrict__ olo, int ncols) {
    int row = blockIdx.x;
    const float* p = in + (size_t)row * ncols;
    size_t ob = (size_t)row * ncols;
    float r = rms_row_scale(p, ncols, threadIdx.x);
    for (int c = threadIdx.x; c < ncols; c += 256) {
        float v = p[c] * r * w[c];
        __half h, l; split_h16(v, h, l);
        ohi[ob + c] = h; olo[ob + c] = l;
    }
}

__global__ __launch_bounds__(256)
void rmsnorm_h(const float* __restrict__ in, const float* __restrict__ w,
               __half* __restrict__ oh, int ncols) {
    int row = blockIdx.x;
    const float* p = in + (size_t)row * ncols;
    size_t ob = (size_t)row * ncols;
    float r = rms_row_scale(p, ncols, threadIdx.x);
    for (int c = threadIdx.x; c < ncols; c += 256)
        oh[ob + c] = __float2half_rn(p[c] * r * w[c]);
}

// ---------------------------------------------------------------------------
// Weight transpose: [K,N] fp32 -> [N,K] fp16 single
// ---------------------------------------------------------------------------
__global__ __launch_bounds__(256)
void wtrans_h(const float* __restrict__ W, __half* __restrict__ T, int K, int N) {
    __shared__ float t[32][33];
    int n0 = blockIdx.x * 32, k0 = blockIdx.y * 32;
    int tx = threadIdx.x & 31, ty = threadIdx.x >> 5;
    #pragma unroll
    for (int i = 0; i < 4; i++) {
        int k = ty + i * 8;
        t[k][tx] = W[(size_t)(k0 + k) * N + n0 + tx];
    }
    __syncthreads();
    #pragma unroll
    for (int i = 0; i < 4; i++) {
        int n = ty + i * 8;
        T[(size_t)(n0 + n) * K + k0 + tx] = __float2half_rn(t[tx][n]);
    }
}

// ---------------------------------------------------------------------------
// GEMM A (qkv): 2-term fp16 (A hi/lo, B single). 128x128, BK=32, 256 thr, occ 2.
// 3-stage cp.async pipeline. Cf = (Ah+Al)*B^T (fp32 out)
// ---------------------------------------------------------------------------
#define APAD 40
#define TILE_B (128 * APAD * 2)     // 10240
#define STAGEA (3 * TILE_B)         // 30720
#define GEMMA_SMEM (3 * STAGEA)     // 92160

__device__ __forceinline__ void load_stage_a2(
    uint32_t st, const char* Ah, const char* Al, const char* B,
    size_t rowb, size_t ko, int tid) {
    #pragma unroll
    for (int i = 0; i < 2; i++) {
        int idx = tid + i * 256;
        int r = idx >> 2, c = idx & 3;
        uint32_t dst = st + (uint32_t)(r * 80 + c * 16);
        size_t src = (size_t)r * rowb + ko + (size_t)c * 16;
        cp16(dst + 0u * TILE_B, Ah + src);
        cp16(dst + 1u * TILE_B, Al + src);
        cp16(dst + 2u * TILE_B, B  + src);
    }
    asm volatile("cp.async.commit_group;" ::: "memory");
}

__global__ __launch_bounds__(256, 2)
void gemm_a2(const __half* __restrict__ Ahi, const __half* __restrict__ Alo,
             const __half* __restrict__ B, float* __restrict__ Cf,
             int M, int N, int K) {
    extern __shared__ char smem[];
    const uint32_t sb = smem_u32(smem);
    const int tid  = threadIdx.x;
    const int warp = tid >> 5, lane = tid & 31;
    const int warp_m = warp & 3;
    const int warp_n = warp >> 2;
    const int bm = blockIdx.y << 7;
    const int bn = blockIdx.x << 7;

    float acc[2][8][4];
    #pragma unroll
    for (int i = 0; i < 2; i++)
        #pragma unroll
        for (int j = 0; j < 8; j++)
            #pragma unroll
            for (int q = 0; q < 4; q++) acc[i][j][q] = 0.f;

    const size_t rowb = (size_t)K * 2;
    const char* Ah0 = (const char*)Ahi + (size_t)bm * rowb;
    const char* Al0 = (const char*)Alo + (size_t)bm * rowb;
    const char* B0  = (const char*)B   + (size_t)bn * rowb;

    const int NIT = K >> 5;
    load_stage_a2(sb, Ah0, Al0, B0, rowb, 0, tid);
    load_stage_a2(sb + STAGEA, Ah0, Al0, B0, rowb, 64, tid);   // FIX: chunk 1 = 64 bytes

    const int arow = warp_m * 32 + (lane & 15);
    const int acolb = ((lane >> 4) << 3);
    const int brow = warp_n * 64 + (lane & 7) + ((lane >> 4) << 3);
    const int bcolb = (lane & 8);

    int bcur = 0, bpre = 2;   // compute buffer, prefetch buffer
    for (int it = 0; it < NIT; it++) {
        if (it + 2 < NIT) {
            load_stage_a2(sb + (uint32_t)(bpre * STAGEA),
                          Ah0, Al0, B0, rowb, (size_t)(it + 2) * 64, tid);
            asm volatile("cp.async.wait_group 2;" ::: "memory");
        } else if (it + 1 < NIT) {
            asm volatile("cp.async.wait_group 1;" ::: "memory");
        } else {
            asm volatile("cp.async.wait_group 0;" ::: "memory");
        }
        __syncthreads();

        const uint32_t st  = sb + (uint32_t)(bcur * STAGEA);
        const uint32_t sah = st;
        const uint32_t sal = st + TILE_B;
        const uint32_t sB  = st + 2u * TILE_B;

        #pragma unroll
        for (int ks = 0; ks < 2; ks++) {
            uint32_t ah[2][4], al[2][4];
            const int acol = ks * 16 + acolb;
            const int bcol = ks * 16 + bcolb;
            #pragma unroll
            for (int mi = 0; mi < 2; mi++) {
                uint32_t off = (uint32_t)(((arow + mi * 16) * APAD + acol) * 2);
                ldsm_x4(ah[mi][0], ah[mi][1], ah[mi][2], ah[mi][3], sah + off);
                ldsm_x4(al[mi][0], al[mi][1], al[mi][2], al[mi][3], sal + off);
            }
            #pragma unroll
            for (int ni = 0; ni < 4; ni++) {
                uint32_t off = (uint32_t)(((brow + ni * 16) * APAD + bcol) * 2);
                uint32_t b0, b1, b2, b3;
                ldsm_x4(b0, b1, b2, b3, sB + off);
                #pragma unroll
                for (int mi = 0; mi < 2; mi++) {
                    mma16816h(acc[mi][2 * ni],     ah[mi], b0, b1);
                    mma16816h(acc[mi][2 * ni + 1], ah[mi], b2, b3);
                    mma16816h(acc[mi][2 * ni],     al[mi], b0, b1);
                    mma16816h(acc[mi][2 * ni + 1], al[mi], b2, b3);
                }
            }
        }
        __syncthreads();
        bcur = (bcur == 2) ? 0 : bcur + 1;
        bpre = (bpre == 2) ? 0 : bpre + 1;
    }

    const int r0 = bm + warp_m * 32 + (lane >> 2);
    const int c0 = bn + warp_n * 64 + 2 * (lane & 3);
    #pragma unroll
    for (int mi = 0; mi < 2; mi++) {
        #pragma unroll
        for (int half = 0; half < 2; half++) {
            int row = r0 + mi * 16 + half * 8;
            size_t rb = (size_t)row * N;
            #pragma unroll
            for (int nj = 0; nj < 8; nj++) {
                int col = c0 + nj * 8;
                *(float2*)&Cf[rb + col] = make_float2(acc[mi][nj][2 * half],
                                                      acc[mi][nj][2 * half + 1]);
            }
        }
    }
}

// ---------------------------------------------------------------------------
// GEMM B: 1-term fp16. 128x128 tile, 256 thr, 2 CTAs/SM. 3-stage pipeline.
// MODE 1: Cf = Res + A*B^T (fp32)   MODE 2: Ch = fp16(srelu(A*B^T))
// ---------------------------------------------------------------------------
#define STAGEH (2 * TILE_B)         // 20480
#define GEMMH_SMEM (3 * STAGEH)     // 61440

__device__ __forceinline__ void load_stageh(
    uint32_t st, const char* A, const char* B,
    size_t rowb, size_t ko, int tid) {
    #pragma unroll
    for (int i = 0; i < 2; i++) {
        int idx = tid + i * 256;
        int r = idx >> 2, c = idx & 3;
        uint32_t dst = st + (uint32_t)(r * 80 + c * 16);
        size_t src = (size_t)r * rowb + ko + (size_t)c * 16;
        cp16(dst + 0u * TILE_B, A + src);
        cp16(dst + 1u * TILE_B, B + src);
    }
    asm volatile("cp.async.commit_group;" ::: "memory");
}

template <int MODE>
__global__ __launch_bounds__(256, 2)
void gemm_h1(const __half* __restrict__ A, const __half* __restrict__ B,
             const float* __restrict__ Res, float* __restrict__ Cf,
             __half* __restrict__ Ch, int M, int N, int K) {
    extern __shared__ char smem[];
    const uint32_t sb = smem_u32(smem);
    const int tid  = threadIdx.x;
    const int warp = tid >> 5, lane = tid & 31;
    const int warp_m = warp & 3;
    const int warp_n = warp >> 2;
    const int bm = blockIdx.y << 7;
    const int bn = blockIdx.x << 7;

    float acc[2][8][4];
    #pragma unroll
    for (int i = 0; i < 2; i++)
        #pragma unroll
        for (int j = 0; j < 8; j++)
            #pragma unroll
            for (int q = 0; q < 4; q++) acc[i][j][q] = 0.f;

    const size_t rowb = (size_t)K * 2;
    const char* A0 = (const char*)A + (size_t)bm * rowb;
    const char* B0 = (const char*)B + (size_t)bn * rowb;

    const int NIT = K >> 5;
    load_stageh(sb, A0, B0, rowb, 0, tid);
    load_stageh(sb + STAGEH, A0, B0, rowb, 64, tid);   // FIX: chunk 1 = 64 bytes

    const int arow = warp_m * 32 + (lane & 15);
    const int acolb = ((lane >> 4) << 3);
    const int brow = warp_n * 64 + (lane & 7) + ((lane >> 4) << 3);
    const int bcolb = (lane & 8);

    int bcur = 0, bpre = 2;
    for (int it = 0; it < NIT; it++) {
        if (it + 2 < NIT) {
            load_stageh(sb + (uint32_t)(bpre * STAGEH),
                        A0, B0, rowb, (size_t)(it + 2) * 64, tid);
            asm volatile("cp.async.wait_group 2;" ::: "memory");
        } else if (it + 1 < NIT) {
            asm volatile("cp.async.wait_group 1;" ::: "memory");
        } else {
            asm volatile("cp.async.wait_group 0;" ::: "memory");
        }
        __syncthreads();

        const uint32_t st = sb + (uint32_t)(bcur * STAGEH);
        const uint32_t sa = st;
        const uint32_t sB = st + TILE_B;

        #pragma unroll
        for (int ks = 0; ks < 2; ks++) {
            uint32_t ah[2][4];
            const int acol = ks * 16 + acolb;
            const int bcol = ks * 16 + bcolb;
            #pragma unroll
            for (int mi = 0; mi < 2; mi++) {
                uint32_t off = (uint32_t)(((arow + mi * 16) * APAD + acol) * 2);
                ldsm_x4(ah[mi][0], ah[mi][1], ah[mi][2], ah[mi][3], sa + off);
            }
            #pragma unroll
            for (int ni = 0; ni < 4; ni++) {
                uint32_t off = (uint32_t)(((brow + ni * 16) * APAD + bcol) * 2);
                uint32_t b0, b1, b2, b3;
                ldsm_x4(b0, b1, b2, b3, sB + off);
                #pragma unroll
                for (int mi = 0; mi < 2; mi++) {
                    mma16816h(acc[mi][2 * ni],     ah[mi], b0, b1);
                    mma16816h(acc[mi][2 * ni + 1], ah[mi], b2, b3);
                }
            }
        }
        __syncthreads();
        bcur = (bcur == 2) ? 0 : bcur + 1;
        bpre = (bpre == 2) ? 0 : bpre + 1;
    }

    const int r0 = bm + warp_m * 32 + (lane >> 2);
    const int c0 = bn + warp_n * 64 + 2 * (lane & 3);
    #pragma unroll
    for (int mi = 0; mi < 2; mi++) {
        #pragma unroll
        for (int half = 0; half < 2; half++) {
            int row = r0 + mi * 16 + half * 8;
            size_t rb = (size_t)row * N;
            #pragma unroll
            for (int nj = 0; nj < 8; nj++) {
                int col = c0 + nj * 8;
                float v0 = acc[mi][nj][2 * half];
                float v1 = acc[mi][nj][2 * half + 1];
                size_t o = rb + col;
                if (MODE == 1) {
                    float2 rv = *(const float2*)&Res[o];
                    *(float2*)&Cf[o] = make_float2(v0 + rv.x, v1 + rv.y);
                } else {
                    float t0 = fmaxf(v0, 0.f); v0 = t0 * t0;
                    float t1 = fmaxf(v1, 0.f); v1 = t1 * t1;
                    *(__half2*)&Ch[o] = __floats2half2_rn(v0, v1);
                }
            }
        }
    }
}

// ---------------------------------------------------------------------------
// MXFP8 qdq (32-element block == one warp)
// ---------------------------------------------------------------------------
__device__ __forceinline__ float qdq32(float x) {
    float a = fabsf(x);
    #pragma unroll
    for (int off = 16; off; off >>= 1) a = fmaxf(a, __shfl_xor_sync(0xffffffffu, a, off));
    a = fmaxf(a, 1e-12f);
    int se = ilogbf(a) + 119;
    se = max(0, min(255, se));
    float scale = exp2f((float)(127 - se));
    float xs = fminf(fmaxf(x * scale, -448.f), 448.f);
    float xq = (float)__nv_fp8_e4m3(xs);
    return xq * exp2f((float)(se - 127));
}

// ---------------------------------------------------------------------------
// QKV post-process: RoPE -> head rmsnorm -> qdq -> (b,h,t,d) fp16 (exact)
// ---------------------------------------------------------------------------
__global__ __launch_bounds__(128)
void qkv_post(const float* __restrict__ qkv, const float* __restrict__ rope,
              const float* __restrict__ qn_w, const float* __restrict__ kn_w,
              __half* __restrict__ gq, __half* __restrict__ gk,
              __half* __restrict__ gv) {
    int idx = blockIdx.x;
    int h  = idx % NH;
    int bt = idx / NH;
    int t  = bt % NT;
    int b  = bt / NT;
    int d  = threadIdx.x;

    const float* base = qkv + (size_t)bt * NC3 + h * ND;
    float qv = base[d];
    float kv = base[NC + d];
    float vv = base[2 * NC + d];

    float fr = rope[t * ND + d];
    float sn, cs;
    sincosf(fr, &sn, &cs);
    __shared__ float sq[ND], sk[ND];
    sq[d] = qv; sk[d] = kv;
    __syncthreads();
    float qr = (d < 64) ? -sq[d + 64] : sq[d - 64];
    float kr = (d < 64) ? -sk[d + 64] : sk[d - 64];
    qv = qv * cs + qr * sn;
    kv = kv * cs + kr * sn;

    float s1 = qv * qv, s2 = kv * kv;
    #pragma unroll
    for (int off = 16; off; off >>= 1) {
        s1 += __shfl_xor_sync(0xffffffffu, s1, off);
        s2 += __shfl_xor_sync(0xffffffffu, s2, off);
    }
    __shared__ float r1[4], r2[4];
    int w = d >> 5, lane = d & 31;
    if (lane == 0) { r1[w] = s1; r2[w] = s2; }
    __syncthreads();
    float ssq = r1[0] + r1[1] + r1[2] + r1[3];
    float ssk = r2[0] + r2[1] + r2[2] + r2[3];
    qv *= rsqrtf(ssq * (1.f / ND) + EPSF) * qn_w[d];
    kv *= rsqrtf(ssk * (1.f / ND) + EPSF) * kn_w[d];

    qv = qdq32(qv);
    kv = qdq32(kv);
    vv = qdq32(vv);

    size_t o = (((size_t)(b * NH + h)) * NT + t) * ND + d;
    gq[o] = __float2half_rn(qv);
    gk[o] = __float2half_rn(kv);
    gv[o] = __float2half_rn(vv);
}

// ---------------------------------------------------------------------------
// Tensor-core causal flash attention (fp16 mma.sync), output fp16 single.
// ---------------------------------------------------------------------------
#define DP 136
#define ATT_Q_ELEMS (128 * DP)
#define ATT_T_ELEMS (64 * DP)
#define ATT_SMEM2 ((ATT_Q_ELEMS + 4 * ATT_T_ELEMS) * 2)

__device__ __forceinline__ void att_load_kv(uint32_t sK, uint32_t sV,
                                            const __half* Kg, const __half* Vg,
                                            int kb, int tid) {
    #pragma unroll
    for (int i = 0; i < 4; i++) {
        int idx = tid + i * 256;
        int r = idx >> 4, c = (idx & 15) << 3;
        uint32_t d = (uint32_t)((r * DP + c) * 2);
        cp16(sK + d, Kg + (size_t)(kb + r) * ND + c);
        cp16(sV + d, Vg + (size_t)(kb + r) * ND + c);
    }
    asm volatile("cp.async.commit_group;" ::: "memory");
}

__global__ __launch_bounds__(256)
void attn_mma(const __half* __restrict__ gq, const __half* __restrict__ gk,
              const __half* __restrict__ gv, __half* __restrict__ ao) {
    extern __shared__ char sm2[];
    const uint32_t sQ = smem_u32(sm2);
    const uint32_t sKV = sQ + ATT_Q_ELEMS * 2;

    const int tid  = threadIdx.x;
    const int warp = tid >> 5, lane = tid & 31;
    const int g  = lane >> 2, qr = lane & 3;
    const int qblk = blockIdx.x;
    const int q0   = qblk << 7;
    const int bh   = blockIdx.y;
    const int b    = bh / NH, h = bh % NH;

    const __half* Qg = gq + ((size_t)bh * NT + q0) * ND;
    const __half* Kg = gk + (size_t)bh * NT * ND;
    const __half* Vg = gv + (size_t)bh * NT * ND;

    #pragma unroll
    for (int i = 0; i < 8; i++) {
        int idx = tid + i * 256;
        int r = idx >> 4, c = (idx & 15) << 3;
        cp16(sQ + (uint32_t)((r * DP + c) * 2), Qg + (size_t)r * ND + c);
    }
    asm volatile("cp.async.commit_group;" ::: "memory");
    att_load_kv(sKV, sKV + ATT_T_ELEMS * 2, Kg, Vg, 0, tid);
    asm volatile("cp.async.wait_group 0;" ::: "memory");
    __syncthreads();

    uint32_t qa[8][4];
    {
        const uint32_t qbase = sQ + (uint32_t)(((warp * 16 + (lane & 15)) * DP
                                                + ((lane >> 4) << 3)) * 2);
        #pragma unroll
        for (int ks = 0; ks < 8; ks++)
            ldsm_x4(qa[ks][0], qa[ks][1], qa[ks][2], qa[ks][3], qbase + ks * 32);
    }

    float oc[16][4];
    #pragma unroll
    for (int i = 0; i < 16; i++)
        #pragma unroll
        for (int j = 0; j < 4; j++) oc[i][j] = 0.f;
    float m0 = -INFINITY, m1 = -INFINITY, l0 = 0.f, l1 = 0.f;
    const int row0 = q0 + warp * 16 + g;
    const int row1 = row0 + 8;
    const int wrow_max = q0 + warp * 16 + 15;

    const int nkt = 2 * qblk + 2;
    for (int kt = 0; kt < nkt; kt++) {
        if (kt + 1 < nkt)
            att_load_kv(sKV + (uint32_t)(((kt + 1) & 1) * 2 * ATT_T_ELEMS * 2),
                        sKV + (uint32_t)((((kt + 1) & 1) * 2 + 1) * ATT_T_ELEMS * 2),
                        Kg, Vg, (kt + 1) << 6, tid);

        const int kb = kt << 6;
        if (kb <= wrow_max) {
            const uint32_t sK = sKV + (uint32_t)((kt & 1) * 2 * ATT_T_ELEMS * 2);
            const uint32_t sV = sK + (uint32_t)(ATT_T_ELEMS * 2);

            float s[8][4];
            #pragma unroll
            for (int j = 0; j < 8; j++)
                #pragma unroll
                for (int q = 0; q < 4; q++) s[j][q] = 0.f;
            #pragma unroll
            for (int np = 0; np < 4; np++) {
                const uint32_t ka = sK + (uint32_t)(((np * 16 + (lane & 7)
                                  + ((lane >> 4) << 3)) * DP + (((lane >> 3) & 1) << 3)) * 2);
                #pragma unroll
                for (int ks = 0; ks < 8; ks++) {
                    uint32_t b0, b1, b2, b3;
                    ldsm_x4(b0, b1, b2, b3, ka + ks * 32);
                    mma16816h(s[2 * np],     qa[ks], b0, b1);
                    mma16816h(s[2 * np + 1], qa[ks], b2, b3);
                }
            }

            float mx0 = -INFINITY, mx1 = -INFINITY;
            #pragma unroll
            for (int j = 0; j < 8; j++) {
                int c0 = kb + j * 8 + qr * 2;
                s[j][0] = (c0     <= row0) ? s[j][0] * ATT_SCALE : -INFINITY;
                s[j][1] = (c0 + 1 <= row0) ? s[j][1] * ATT_SCALE : -INFINITY;
                s[j][2] = (c0     <= row1) ? s[j][2] * ATT_SCALE : -INFINITY;
                s[j][3] = (c0 + 1 <= row1) ? s[j][3] * ATT_SCALE : -INFINITY;
                mx0 = fmaxf(mx0, fmaxf(s[j][0], s[j][1]));
                mx1 = fmaxf(mx1, fmaxf(s[j][2], s[j][3]));
            }
            mx0 = fmaxf(mx0, __shfl_xor_sync(0xffffffffu, mx0, 1));
            mx0 = fmaxf(mx0, __shfl_xor_sync(0xffffffffu, mx0, 2));
            mx1 = fmaxf(mx1, __shfl_xor_sync(0xffffffffu, mx1, 1));
            mx1 = fmaxf(mx1, __shfl_xor_sync(0xffffffffu, mx1, 2));

            float mn0 = fmaxf(m0, mx0), mn1 = fmaxf(m1, mx1);
            float al0 = __expf(m0 - mn0), al1 = __expf(m1 - mn1);
            m0 = mn0; m1 = mn1;

            uint32_t ph[8][2];
            float ls0 = 0.f, ls1 = 0.f;
            #pragma unroll
            for (int j = 0; j < 8; j++) {
                float p0 = __expf(s[j][0] - mn0);
                float p1 = __expf(s[j][1] - mn0);
                float p2 = __expf(s[j][2] - mn1);
                float p3 = __expf(s[j][3] - mn1);
                ls0 += p0 + p1; ls1 += p2 + p3;
                ph[j][0] = pack_h2(p0, p1);
                ph[j][1] = pack_h2(p2, p3);
            }
            l0 = l0 * al0 + ls0;
            l1 = l1 * al1 + ls1;

            #pragma unroll
            for (int nt = 0; nt < 16; nt++) {
                oc[nt][0] *= al0; oc[nt][1] *= al0;
                oc[nt][2] *= al1; oc[nt][3] *= al1;
            }

            #pragma unroll
            for (int ks = 0; ks < 4; ks++) {
                uint32_t pa[4] = { ph[2*ks][0], ph[2*ks][1], ph[2*ks+1][0], ph[2*ks+1][1] };
                const uint32_t va0 = sV + (uint32_t)(((ks * 16 + (lane & 7)
                                   + ((lane >> 3) & 1) * 8) * DP + ((lane >> 4) << 3)) * 2);
                #pragma unroll
                for (int np = 0; np < 8; np++) {
                    uint32_t b0, b1, b2, b3;
                    ldsm_x4t(b0, b1, b2, b3, va0 + np * 32);
                    mma16816h(oc[2 * np],     pa, b0, b1);
                    mma16816h(oc[2 * np + 1], pa, b2, b3);
                }
            }
        }

        if (kt + 1 < nkt)
            asm volatile("cp.async.wait_group 0;" ::: "memory");
        __syncthreads();
    }

    l0 += __shfl_xor_sync(0xffffffffu, l0, 1);
    l0 += __shfl_xor_sync(0xffffffffu, l0, 2);
    l1 += __shfl_xor_sync(0xffffffffu, l1, 1);
    l1 += __shfl_xor_sync(0xffffffffu, l1, 2);

    const float li0 = 1.f / l0, li1 = 1.f / l1;
    const size_t ob0 = ((size_t)b * NT + row0) * NC + h * ND;
    const size_t ob1 = ((size_t)b * NT + row1) * NC + h * ND;
    #pragma unroll
    for (int nt = 0; nt < 16; nt++) {
        int col = nt * 8 + qr * 2;
        *(__half2*)&ao[ob0 + col] = __floats2half2_rn(oc[nt][0] * li0, oc[nt][1] * li0);
        *(__half2*)&ao[ob1 + col] = __floats2half2_rn(oc[nt][2] * li1, oc[nt][3] * li1);
    }
}

// ---------------------------------------------------------------------------
// Launch
// ---------------------------------------------------------------------------
extern "C" void kernel_launch(void* const* d_in, const int* in_sizes, int n_in,
                              void* d_out, int out_size) {
    const float* x      = (const float*)d_in[0];
    const float* rope   = (const float*)d_in[1];
    const float* ln1_w  = (const float*)d_in[2];
    const float* w_qkv  = (const float*)d_in[3];
    const float* qn_w   = (const float*)d_in[4];
    const float* kn_w   = (const float*)d_in[5];
    const float* w_out  = (const float*)d_in[6];
    const float* ln2_w  = (const float*)d_in[7];
    const float* w_fc1  = (const float*)d_in[8];
    const float* w_fc2  = (const float*)d_in[9];
    float* out = (float*)d_out;

    float *qkv, *y1;
    __half *qb, *kb, *vb, *ao, *hb, *xn16, *xnh, *xnl;
    __half *wqT, *woT, *w1T, *w2T;
    cudaGetSymbolAddress((void**)&xnh, g_xn_hi);
    cudaGetSymbolAddress((void**)&xnl, g_xn_lo);
    cudaGetSymbolAddress((void**)&xn16, g_xn16);
    cudaGetSymbolAddress((void**)&qkv, g_qkv);
    cudaGetSymbolAddress((void**)&qb,  g_qb);
    cudaGetSymbolAddress((void**)&kb,  g_kb);
    cudaGetSymbolAddress((void**)&vb,  g_vb);
    cudaGetSymbolAddress((void**)&ao,  g_ao);
    cudaGetSymbolAddress((void**)&y1,  g_y1);
    cudaGetSymbolAddress((void**)&hb,  g_hb);
    cudaGetSymbolAddress((void**)&wqT, g_wqkvT);
    cudaGetSymbolAddress((void**)&woT, g_woutT);
    cudaGetSymbolAddress((void**)&w1T, g_wfc1T);
    cudaGetSymbolAddress((void**)&w2T, g_wfc2T);

    cudaFuncSetAttribute(attn_mma, cudaFuncAttributeMaxDynamicSharedMemorySize, ATT_SMEM2);
    cudaFuncSetAttribute(gemm_a2, cudaFuncAttributeMaxDynamicSharedMemorySize, GEMMA_SMEM);
    cudaFuncSetAttribute(gemm_h1<1>, cudaFuncAttributeMaxDynamicSharedMemorySize, GEMMH_SMEM);
    cudaFuncSetAttribute(gemm_h1<2>, cudaFuncAttributeMaxDynamicSharedMemorySize, GEMMH_SMEM);

    // Weight transpose (all fp16 single)
    wtrans_h<<<dim3(NC3 / 32, NC / 32), 256>>>(w_qkv, wqT, NC, NC3);
    wtrans_h<<<dim3(NC  / 32, NC / 32), 256>>>(w_out, woT, NC, NC);
    wtrans_h<<<dim3(NF  / 32, NC / 32), 256>>>(w_fc1, w1T, NC, NF);
    wtrans_h<<<dim3(NC  / 32, NF / 32), 256>>>(w_fc2, w2T, NF, NC);

    // 1) rmsnorm(x) -> hi/lo fp16
    rmsnorm_split_h<<<NBT, 256>>>(x, ln1_w, xnh, xnl, NC);

    // 2) qkv = xn @ w_qkv (fp32 out), 2-term fp16 (A hi/lo, B single)
    gemm_a2<<<dim3(NC3 / 128, NBT / 128), 256, GEMMA_SMEM>>>(
        xnh, xnl, wqT, qkv, NBT, NC3, NC);

    // 3) RoPE + head rmsnorm + mxfp8 qdq -> fp16 (exact)
    qkv_post<<<NB * NT * NH, 128>>>(qkv, rope, qn_w, kn_w, qb, kb, vb);

    // 4) tensor-core causal attention -> fp16 single
    attn_mma<<<dim3(NT / 128, NB * NH), 256, ATT_SMEM2>>>(qb, kb, vb, ao);

    // 5) y1 = x + attn @ w_out   (1-term fp16)
    gemm_h1<1><<<dim3(NC / 128, NBT / 128), 256, GEMMH_SMEM>>>(
        ao, woT, x, y1, nullptr, NBT, NC, NC);

    // 6) rmsnorm(y1) -> fp16 single
    rmsnorm_h<<<NBT, 256>>>(y1, ln2_w, xn16, NC);

    // 7) h = srelu(xn @ w_fc1) -> fp16 single   (1-term fp16)
    gemm_h1<2><<<dim3(NF / 128, NBT / 128), 256, GEMMH_SMEM>>>(
        xn16, w1T, nullptr, nullptr, hb, NBT, NF, NC);

    // 8) out = y1 + h @ w_fc2   (1-term fp16)
    gemm_h1<1><<<dim3(NC / 128, NBT / 128), 256, GEMMH_SMEM>>>(
        hb, w2T, y1, out, nullptr, NBT, NC, NF);
}

// round 14
// speedup vs baseline: 1.1170x; 1.1170x over previous
#include <cuda_runtime.h>
#include <cuda_bf16.h>
#include <cuda_fp16.h>
#include <cuda_fp8.h>
#include <math.h>
#include <stdint.h>

// Problem constants
#define NB 4
#define NT 2048
#define NC 1280
#define NH 10
#define ND 128
#define NF 5120
#define NBT (NB*NT)          // 8192
#define NC3 (3*NC)           // 3840
#define EPSF 1e-5f
#define ATT_SCALE 0.08838834764831845f   // 1/sqrt(128)

// ---------------------------------------------------------------------------
// Scratch (device globals)
// ---------------------------------------------------------------------------
__device__ __half g_xn_hi[(size_t)NBT * NC];
__device__ __half g_xn_lo[(size_t)NBT * NC];
__device__ __half g_xn16[(size_t)NBT * NC];
__device__ float g_qkv[(size_t)NBT * NC3];
__device__ __half g_qb[(size_t)NB * NH * NT * ND];
__device__ __half g_kb[(size_t)NB * NH * NT * ND];
__device__ __half g_vb[(size_t)NB * NH * NT * ND];
__device__ __half g_ao[(size_t)NBT * NC];
__device__ float g_y1 [(size_t)NBT * NC];
__device__ __half g_hb[(size_t)NBT * NF];
// transposed weights [N,K], fp16 single
__device__ __half g_wqkvT[(size_t)NC3 * NC];
__device__ __half g_woutT[(size_t)NC * NC];
__device__ __half g_wfc1T[(size_t)NF * NC];
__device__ __half g_wfc2T[(size_t)NC * NF];

// ---------------------------------------------------------------------------
// PTX helpers
// ---------------------------------------------------------------------------
__device__ __forceinline__ uint32_t smem_u32(const void* p) {
    uint32_t a;
    asm("{ .reg .u64 t; cvta.to.shared.u64 t, %1; cvt.u32.u64 %0, t; }" : "=r"(a) : "l"(p));
    return a;
}
__device__ __forceinline__ void cp16(uint32_t dst, const void* src) {
    asm volatile("cp.async.cg.shared.global [%0], [%1], 16;" :: "r"(dst), "l"(src));
}
__device__ __forceinline__ void ldsm_x4(uint32_t& r0, uint32_t& r1, uint32_t& r2,
                                        uint32_t& r3, uint32_t addr) {
    asm volatile("ldmatrix.sync.aligned.m8n8.x4.shared.b16 {%0,%1,%2,%3}, [%4];"
                 : "=r"(r0), "=r"(r1), "=r"(r2), "=r"(r3) : "r"(addr));
}
__device__ __forceinline__ void ldsm_x4t(uint32_t& r0, uint32_t& r1, uint32_t& r2,
                                         uint32_t& r3, uint32_t addr) {
    asm volatile("ldmatrix.sync.aligned.m8n8.x4.trans.shared.b16 {%0,%1,%2,%3}, [%4];"
                 : "=r"(r0), "=r"(r1), "=r"(r2), "=r"(r3) : "r"(addr));
}
__device__ __forceinline__ void mma16816h(float* c, const uint32_t* a,
                                          uint32_t b0, uint32_t b1) {
    asm volatile(
        "mma.sync.aligned.m16n8k16.row.col.f32.f16.f16.f32 "
        "{%0,%1,%2,%3}, {%4,%5,%6,%7}, {%8,%9}, {%0,%1,%2,%3};"
        : "+f"(c[0]), "+f"(c[1]), "+f"(c[2]), "+f"(c[3])
        : "r"(a[0]), "r"(a[1]), "r"(a[2]), "r"(a[3]), "r"(b0), "r"(b1));
}

// ---------------------------------------------------------------------------
// splits / packs
// ---------------------------------------------------------------------------
__device__ __forceinline__ void split_h16(float v, __half& h, __half& l) {
    h = __float2half_rn(v);
    l = __float2half_rn(v - __half2float(h));
}
__device__ __forceinline__ uint32_t pack_h2(float lo, float hi) {
    __half2 t = __floats2half2_rn(lo, hi);
    return *(uint32_t*)&t;
}

// ---------------------------------------------------------------------------
// RMSNorm variants
// ---------------------------------------------------------------------------
__device__ __forceinline__ float rms_row_scale(const float* p, int ncols, int tid) {
    float ss = 0.f;
    for (int c = tid; c < ncols; c += 256) { float v = p[c]; ss = fmaf(v, v, ss); }
    #pragma unroll
    for (int off = 16; off; off >>= 1) ss += __shfl_xor_sync(0xffffffffu, ss, off);
    __shared__ float red[8];
    int wid = tid >> 5, lane = tid & 31;
    if (lane == 0) red[wid] = ss;
    __syncthreads();
    float tot = 0.f;
    #pragma unroll
    for (int i = 0; i < 8; i++) tot += red[i];
    return rsqrtf(tot / (float)ncols + EPSF);
}

__global__ __launch_bounds__(256)
void rmsnorm_split_h(const float* __restrict__ in, const float* __restrict__ w,
                     __half* __restrict__ ohi, __half* __restrict__ olo, int ncols) {
    int row = blockIdx.x;
    const float* p = in + (size_t)row * ncols;
    size_t ob = (size_t)row * ncols;
    float r = rms_row_scale(p, ncols, threadIdx.x);
    for (int c = threadIdx.x; c < ncols; c += 256) {
        float v = p[c] * r * w[c];
        __half h, l; split_h16(v, h, l);
        ohi[ob + c] = h; olo[ob + c] = l;
    }
}

__global__ __launch_bounds__(256)
void rmsnorm_h(const float* __restrict__ in, const float* __restrict__ w,
               __half* __restrict__ oh, int ncols) {
    int row = blockIdx.x;
    const float* p = in + (size_t)row * ncols;
    size_t ob = (size_t)row * ncols;
    float r = rms_row_scale(p, ncols, threadIdx.x);
    for (int c = threadIdx.x; c < ncols; c += 256)
        oh[ob + c] = __float2half_rn(p[c] * r * w[c]);
}

// ---------------------------------------------------------------------------
// Weight transpose: [K,N] fp32 -> [N,K] fp16 single
// ---------------------------------------------------------------------------
__global__ __launch_bounds__(256)
void wtrans_h(const float* __restrict__ W, __half* __restrict__ T, int K, int N) {
    __shared__ float t[32][33];
    int n0 = blockIdx.x * 32, k0 = blockIdx.y * 32;
    int tx = threadIdx.x & 31, ty = threadIdx.x >> 5;
    #pragma unroll
    for (int i = 0; i < 4; i++) {
        int k = ty + i * 8;
        t[k][tx] = W[(size_t)(k0 + k) * N + n0 + tx];
    }
    __syncthreads();
    #pragma unroll
    for (int i = 0; i < 4; i++) {
        int n = ty + i * 8;
        T[(size_t)(n0 + n) * K + k0 + tx] = __float2half_rn(t[tx][n]);
    }
}

// ---------------------------------------------------------------------------
// GEMM tiles: BK=64, row stride 72 halfs (144 B) — ldsm conflict-free
// ---------------------------------------------------------------------------
#define APAD64 72
#define TILE64 (128 * APAD64 * 2)   // 18432 bytes

// ---------------------------------------------------------------------------
// GEMM A (qkv): 2-term fp16 (A hi/lo, B single). 128x128, BK=64, 2-stage, occ 2.
// ---------------------------------------------------------------------------
#define STAGEA (3 * TILE64)         // 55296
#define GEMMA_SMEM (2 * STAGEA)     // 110592

__device__ __forceinline__ void load_stage_a2(
    uint32_t st, const char* Ah, const char* Al, const char* B,
    size_t rowb, size_t ko, int tid) {
    #pragma unroll
    for (int i = 0; i < 4; i++) {
        int idx = tid + i * 256;
        int r = idx >> 3, c = idx & 7;
        uint32_t dst = st + (uint32_t)(r * 144 + c * 16);
        size_t src = (size_t)r * rowb + ko + (size_t)c * 16;
        cp16(dst + 0u * TILE64, Ah + src);
        cp16(dst + 1u * TILE64, Al + src);
        cp16(dst + 2u * TILE64, B  + src);
    }
    asm volatile("cp.async.commit_group;" ::: "memory");
}

__global__ __launch_bounds__(256, 2)
void gemm_a2(const __half* __restrict__ Ahi, const __half* __restrict__ Alo,
             const __half* __restrict__ B, float* __restrict__ Cf,
             int M, int N, int K) {
    extern __shared__ char smem[];
    const uint32_t sb = smem_u32(smem);
    const int tid  = threadIdx.x;
    const int warp = tid >> 5, lane = tid & 31;
    const int warp_m = warp & 3;
    const int warp_n = warp >> 2;
    const int bm = blockIdx.y << 7;
    const int bn = blockIdx.x << 7;

    float acc[2][8][4];
    #pragma unroll
    for (int i = 0; i < 2; i++)
        #pragma unroll
        for (int j = 0; j < 8; j++)
            #pragma unroll
            for (int q = 0; q < 4; q++) acc[i][j][q] = 0.f;

    const size_t rowb = (size_t)K * 2;
    const char* Ah0 = (const char*)Ahi + (size_t)bm * rowb;
    const char* Al0 = (const char*)Alo + (size_t)bm * rowb;
    const char* B0  = (const char*)B   + (size_t)bn * rowb;

    const int NIT = K >> 6;   // BK = 64
    load_stage_a2(sb, Ah0, Al0, B0, rowb, 0, tid);

    const int arow = warp_m * 32 + (lane & 15);
    const int acolb = ((lane >> 4) << 3);
    const int brow = warp_n * 64 + (lane & 7) + ((lane >> 4) << 3);
    const int bcolb = (lane & 8);

    for (int it = 0; it < NIT; it++) {
        if (it + 1 < NIT) {
            load_stage_a2(sb + (uint32_t)(((it + 1) & 1) * STAGEA),
                          Ah0, Al0, B0, rowb, (size_t)(it + 1) * 128, tid);
            asm volatile("cp.async.wait_group 1;" ::: "memory");
        } else {
            asm volatile("cp.async.wait_group 0;" ::: "memory");
        }
        __syncthreads();

        const uint32_t st  = sb + (uint32_t)((it & 1) * STAGEA);
        const uint32_t sah = st;
        const uint32_t sal = st + TILE64;
        const uint32_t sB  = st + 2u * TILE64;

        #pragma unroll
        for (int ks = 0; ks < 4; ks++) {
            uint32_t ah[2][4], al[2][4];
            const int acol = ks * 16 + acolb;
            const int bcol = ks * 16 + bcolb;
            #pragma unroll
            for (int mi = 0; mi < 2; mi++) {
                uint32_t off = (uint32_t)(((arow + mi * 16) * APAD64 + acol) * 2);
                ldsm_x4(ah[mi][0], ah[mi][1], ah[mi][2], ah[mi][3], sah + off);
                ldsm_x4(al[mi][0], al[mi][1], al[mi][2], al[mi][3], sal + off);
            }
            #pragma unroll
            for (int ni = 0; ni < 4; ni++) {
                uint32_t off = (uint32_t)(((brow + ni * 16) * APAD64 + bcol) * 2);
                uint32_t b0, b1, b2, b3;
                ldsm_x4(b0, b1, b2, b3, sB + off);
                #pragma unroll
                for (int mi = 0; mi < 2; mi++) {
                    mma16816h(acc[mi][2 * ni],     ah[mi], b0, b1);
                    mma16816h(acc[mi][2 * ni + 1], ah[mi], b2, b3);
                    mma16816h(acc[mi][2 * ni],     al[mi], b0, b1);
                    mma16816h(acc[mi][2 * ni + 1], al[mi], b2, b3);
                }
            }
        }
        __syncthreads();
    }

    const int r0 = bm + warp_m * 32 + (lane >> 2);
    const int c0 = bn + warp_n * 64 + 2 * (lane & 3);
    #pragma unroll
    for (int mi = 0; mi < 2; mi++) {
        #pragma unroll
        for (int half = 0; half < 2; half++) {
            int row = r0 + mi * 16 + half * 8;
            size_t rb = (size_t)row * N;
            #pragma unroll
            for (int nj = 0; nj < 8; nj++) {
                int col = c0 + nj * 8;
                *(float2*)&Cf[rb + col] = make_float2(acc[mi][nj][2 * half],
                                                      acc[mi][nj][2 * half + 1]);
            }
        }
    }
}

// ---------------------------------------------------------------------------
// GEMM B: 1-term fp16. 128x128 tile, BK=64, 2-stage, occ 2.
// MODE 1: Cf = Res + A*B^T (fp32)   MODE 2: Ch = fp16(srelu(A*B^T))
// ---------------------------------------------------------------------------
#define STAGEH (2 * TILE64)         // 36864
#define GEMMH_SMEM (2 * STAGEH)     // 73728

__device__ __forceinline__ void load_stageh(
    uint32_t st, const char* A, const char* B,
    size_t rowb, size_t ko, int tid) {
    #pragma unroll
    for (int i = 0; i < 4; i++) {
        int idx = tid + i * 256;
        int r = idx >> 3, c = idx & 7;
        uint32_t dst = st + (uint32_t)(r * 144 + c * 16);
        size_t src = (size_t)r * rowb + ko + (size_t)c * 16;
        cp16(dst + 0u * TILE64, A + src);
        cp16(dst + 1u * TILE64, B + src);
    }
    asm volatile("cp.async.commit_group;" ::: "memory");
}

template <int MODE>
__global__ __launch_bounds__(256, 2)
void gemm_h1(const __half* __restrict__ A, const __half* __restrict__ B,
             const float* __restrict__ Res, float* __restrict__ Cf,
             __half* __restrict__ Ch, int M, int N, int K) {
    extern __shared__ char smem[];
    const uint32_t sb = smem_u32(smem);
    const int tid  = threadIdx.x;
    const int warp = tid >> 5, lane = tid & 31;
    const int warp_m = warp & 3;
    const int warp_n = warp >> 2;
    const int bm = blockIdx.y << 7;
    const int bn = blockIdx.x << 7;

    float acc[2][8][4];
    #pragma unroll
    for (int i = 0; i < 2; i++)
        #pragma unroll
        for (int j = 0; j < 8; j++)
            #pragma unroll
            for (int q = 0; q < 4; q++) acc[i][j][q] = 0.f;

    const size_t rowb = (size_t)K * 2;
    const char* A0 = (const char*)A + (size_t)bm * rowb;
    const char* B0 = (const char*)B + (size_t)bn * rowb;

    const int NIT = K >> 6;   // BK = 64
    load_stageh(sb, A0, B0, rowb, 0, tid);

    const int arow = warp_m * 32 + (lane & 15);
    const int acolb = ((lane >> 4) << 3);
    const int brow = warp_n * 64 + (lane & 7) + ((lane >> 4) << 3);
    const int bcolb = (lane & 8);

    for (int it = 0; it < NIT; it++) {
        if (it + 1 < NIT) {
            load_stageh(sb + (uint32_t)(((it + 1) & 1) * STAGEH),
                        A0, B0, rowb, (size_t)(it + 1) * 128, tid);
            asm volatile("cp.async.wait_group 1;" ::: "memory");
        } else {
            asm volatile("cp.async.wait_group 0;" ::: "memory");
        }
        __syncthreads();

        const uint32_t st = sb + (uint32_t)((it & 1) * STAGEH);
        const uint32_t sa = st;
        const uint32_t sB = st + TILE64;

        #pragma unroll
        for (int ks = 0; ks < 4; ks++) {
            uint32_t ah[2][4];
            const int acol = ks * 16 + acolb;
            const int bcol = ks * 16 + bcolb;
            #pragma unroll
            for (int mi = 0; mi < 2; mi++) {
                uint32_t off = (uint32_t)(((arow + mi * 16) * APAD64 + acol) * 2);
                ldsm_x4(ah[mi][0], ah[mi][1], ah[mi][2], ah[mi][3], sa + off);
            }
            #pragma unroll
            for (int ni = 0; ni < 4; ni++) {
                uint32_t off = (uint32_t)(((brow + ni * 16) * APAD64 + bcol) * 2);
                uint32_t b0, b1, b2, b3;
                ldsm_x4(b0, b1, b2, b3, sB + off);
                #pragma unroll
                for (int mi = 0; mi < 2; mi++) {
                    mma16816h(acc[mi][2 * ni],     ah[mi], b0, b1);
                    mma16816h(acc[mi][2 * ni + 1], ah[mi], b2, b3);
                }
            }
        }
        __syncthreads();
    }

    const int r0 = bm + warp_m * 32 + (lane >> 2);
    const int c0 = bn + warp_n * 64 + 2 * (lane & 3);
    #pragma unroll
    for (int mi = 0; mi < 2; mi++) {
        #pragma unroll
        for (int half = 0; half < 2; half++) {
            int row = r0 + mi * 16 + half * 8;
            size_t rb = (size_t)row * N;
            #pragma unroll
            for (int nj = 0; nj < 8; nj++) {
                int col = c0 + nj * 8;
                float v0 = acc[mi][nj][2 * half];
                float v1 = acc[mi][nj][2 * half + 1];
                size_t o = rb + col;
                if (MODE == 1) {
                    float2 rv = *(const float2*)&Res[o];
                    *(float2*)&Cf[o] = make_float2(v0 + rv.x, v1 + rv.y);
                } else {
                    float t0 = fmaxf(v0, 0.f); v0 = t0 * t0;
                    float t1 = fmaxf(v1, 0.f); v1 = t1 * t1;
                    *(__half2*)&Ch[o] = __floats2half2_rn(v0, v1);
                }
            }
        }
    }
}

// ---------------------------------------------------------------------------
// MXFP8 qdq (32-element block == one warp)
// ---------------------------------------------------------------------------
__device__ __forceinline__ float qdq32(float x) {
    float a = fabsf(x);
    #pragma unroll
    for (int off = 16; off; off >>= 1) a = fmaxf(a, __shfl_xor_sync(0xffffffffu, a, off));
    a = fmaxf(a, 1e-12f);
    int se = ilogbf(a) + 119;
    se = max(0, min(255, se));
    float scale = exp2f((float)(127 - se));
    float xs = fminf(fmaxf(x * scale, -448.f), 448.f);
    float xq = (float)__nv_fp8_e4m3(xs);
    return xq * exp2f((float)(se - 127));
}

// ---------------------------------------------------------------------------
// QKV post-process: RoPE -> head rmsnorm -> qdq -> (b,h,t,d) fp16 (exact)
// ---------------------------------------------------------------------------
__global__ __launch_bounds__(128)
void qkv_post(const float* __restrict__ qkv, const float* __restrict__ rope,
              const float* __restrict__ qn_w, const float* __restrict__ kn_w,
              __half* __restrict__ gq, __half* __restrict__ gk,
              __half* __restrict__ gv) {
    int idx = blockIdx.x;
    int h  = idx % NH;
    int bt = idx / NH;
    int t  = bt % NT;
    int b  = bt / NT;
    int d  = threadIdx.x;

    const float* base = qkv + (size_t)bt * NC3 + h * ND;
    float qv = base[d];
    float kv = base[NC + d];
    float vv = base[2 * NC + d];

    float fr = rope[t * ND + d];
    float sn, cs;
    sincosf(fr, &sn, &cs);
    __shared__ float sq[ND], sk[ND];
    sq[d] = qv; sk[d] = kv;
    __syncthreads();
    float qr = (d < 64) ? -sq[d + 64] : sq[d - 64];
    float kr = (d < 64) ? -sk[d + 64] : sk[d - 64];
    qv = qv * cs + qr * sn;
    kv = kv * cs + kr * sn;

    float s1 = qv * qv, s2 = kv * kv;
    #pragma unroll
    for (int off = 16; off; off >>= 1) {
        s1 += __shfl_xor_sync(0xffffffffu, s1, off);
        s2 += __shfl_xor_sync(0xffffffffu, s2, off);
    }
    __shared__ float r1[4], r2[4];
    int w = d >> 5, lane = d & 31;
    if (lane == 0) { r1[w] = s1; r2[w] = s2; }
    __syncthreads();
    float ssq = r1[0] + r1[1] + r1[2] + r1[3];
    float ssk = r2[0] + r2[1] + r2[2] + r2[3];
    qv *= rsqrtf(ssq * (1.f / ND) + EPSF) * qn_w[d];
    kv *= rsqrtf(ssk * (1.f / ND) + EPSF) * kn_w[d];

    qv = qdq32(qv);
    kv = qdq32(kv);
    vv = qdq32(vv);

    size_t o = (((size_t)(b * NH + h)) * NT + t) * ND + d;
    gq[o] = __float2half_rn(qv);
    gk[o] = __float2half_rn(kv);
    gv[o] = __float2half_rn(vv);
}

// ---------------------------------------------------------------------------
// Tensor-core causal flash attention (fp16 mma.sync), output fp16 single.
// ---------------------------------------------------------------------------
#define DP 136
#define ATT_Q_ELEMS (128 * DP)
#define ATT_T_ELEMS (64 * DP)
#define ATT_SMEM2 ((ATT_Q_ELEMS + 4 * ATT_T_ELEMS) * 2)

__device__ __forceinline__ void att_load_kv(uint32_t sK, uint32_t sV,
                                            const __half* Kg, const __half* Vg,
                                            int kb, int tid) {
    #pragma unroll
    for (int i = 0; i < 4; i++) {
        int idx = tid + i * 256;
        int r = idx >> 4, c = (idx & 15) << 3;
        uint32_t d = (uint32_t)((r * DP + c) * 2);
        cp16(sK + d, Kg + (size_t)(kb + r) * ND + c);
        cp16(sV + d, Vg + (size_t)(kb + r) * ND + c);
    }
    asm volatile("cp.async.commit_group;" ::: "memory");
}

__global__ __launch_bounds__(256)
void attn_mma(const __half* __restrict__ gq, const __half* __restrict__ gk,
              const __half* __restrict__ gv, __half* __restrict__ ao) {
    extern __shared__ char sm2[];
    const uint32_t sQ = smem_u32(sm2);
    const uint32_t sKV = sQ + ATT_Q_ELEMS * 2;

    const int tid  = threadIdx.x;
    const int warp = tid >> 5, lane = tid & 31;
    const int g  = lane >> 2, qr = lane & 3;
    const int qblk = blockIdx.x;
    const int q0   = qblk << 7;
    const int bh   = blockIdx.y;
    const int b    = bh / NH, h = bh % NH;

    const __half* Qg = gq + ((size_t)bh * NT + q0) * ND;
    const __half* Kg = gk + (size_t)bh * NT * ND;
    const __half* Vg = gv + (size_t)bh * NT * ND;

    #pragma unroll
    for (int i = 0; i < 8; i++) {
        int idx = tid + i * 256;
        int r = idx >> 4, c = (idx & 15) << 3;
        cp16(sQ + (uint32_t)((r * DP + c) * 2), Qg + (size_t)r * ND + c);
    }
    asm volatile("cp.async.commit_group;" ::: "memory");
    att_load_kv(sKV, sKV + ATT_T_ELEMS * 2, Kg, Vg, 0, tid);
    asm volatile("cp.async.wait_group 0;" ::: "memory");
    __syncthreads();

    uint32_t qa[8][4];
    {
        const uint32_t qbase = sQ + (uint32_t)(((warp * 16 + (lane & 15)) * DP
                                                + ((lane >> 4) << 3)) * 2);
        #pragma unroll
        for (int ks = 0; ks < 8; ks++)
            ldsm_x4(qa[ks][0], qa[ks][1], qa[ks][2], qa[ks][3], qbase + ks * 32);
    }

    float oc[16][4];
    #pragma unroll
    for (int i = 0; i < 16; i++)
        #pragma unroll
        for (int j = 0; j < 4; j++) oc[i][j] = 0.f;
    float m0 = -INFINITY, m1 = -INFINITY, l0 = 0.f, l1 = 0.f;
    const int row0 = q0 + warp * 16 + g;
    const int row1 = row0 + 8;
    const int wrow_max = q0 + warp * 16 + 15;

    const int nkt = 2 * qblk + 2;
    for (int kt = 0; kt < nkt; kt++) {
        if (kt + 1 < nkt)
            att_load_kv(sKV + (uint32_t)(((kt + 1) & 1) * 2 * ATT_T_ELEMS * 2),
                        sKV + (uint32_t)((((kt + 1) & 1) * 2 + 1) * ATT_T_ELEMS * 2),
                        Kg, Vg, (kt + 1) << 6, tid);

        const int kb = kt << 6;
        if (kb <= wrow_max) {
            const uint32_t sK = sKV + (uint32_t)((kt & 1) * 2 * ATT_T_ELEMS * 2);
            const uint32_t sV = sK + (uint32_t)(ATT_T_ELEMS * 2);

            float s[8][4];
            #pragma unroll
            for (int j = 0; j < 8; j++)
                #pragma unroll
                for (int q = 0; q < 4; q++) s[j][q] = 0.f;
            #pragma unroll
            for (int np = 0; np < 4; np++) {
                const uint32_t ka = sK + (uint32_t)(((np * 16 + (lane & 7)
                                  + ((lane >> 4) << 3)) * DP + (((lane >> 3) & 1) << 3)) * 2);
                #pragma unroll
                for (int ks = 0; ks < 8; ks++) {
                    uint32_t b0, b1, b2, b3;
                    ldsm_x4(b0, b1, b2, b3, ka + ks * 32);
                    mma16816h(s[2 * np],     qa[ks], b0, b1);
                    mma16816h(s[2 * np + 1], qa[ks], b2, b3);
                }
            }

            float mx0 = -INFINITY, mx1 = -INFINITY;
            #pragma unroll
            for (int j = 0; j < 8; j++) {
                int c0 = kb + j * 8 + qr * 2;
                s[j][0] = (c0     <= row0) ? s[j][0] * ATT_SCALE : -INFINITY;
                s[j][1] = (c0 + 1 <= row0) ? s[j][1] * ATT_SCALE : -INFINITY;
                s[j][2] = (c0     <= row1) ? s[j][2] * ATT_SCALE : -INFINITY;
                s[j][3] = (c0 + 1 <= row1) ? s[j][3] * ATT_SCALE : -INFINITY;
                mx0 = fmaxf(mx0, fmaxf(s[j][0], s[j][1]));
                mx1 = fmaxf(mx1, fmaxf(s[j][2], s[j][3]));
            }
            mx0 = fmaxf(mx0, __shfl_xor_sync(0xffffffffu, mx0, 1));
            mx0 = fmaxf(mx0, __shfl_xor_sync(0xffffffffu, mx0, 2));
            mx1 = fmaxf(mx1, __shfl_xor_sync(0xffffffffu, mx1, 1));
            mx1 = fmaxf(mx1, __shfl_xor_sync(0xffffffffu, mx1, 2));

            float mn0 = fmaxf(m0, mx0), mn1 = fmaxf(m1, mx1);
            float al0 = __expf(m0 - mn0), al1 = __expf(m1 - mn1);
            m0 = mn0; m1 = mn1;

            uint32_t ph[8][2];
            float ls0 = 0.f, ls1 = 0.f;
            #pragma unroll
            for (int j = 0; j < 8; j++) {
                float p0 = __expf(s[j][0] - mn0);
                float p1 = __expf(s[j][1] - mn0);
                float p2 = __expf(s[j][2] - mn1);
                float p3 = __expf(s[j][3] - mn1);
                ls0 += p0 + p1; ls1 += p2 + p3;
                ph[j][0] = pack_h2(p0, p1);
                ph[j][1] = pack_h2(p2, p3);
            }
            l0 = l0 * al0 + ls0;
            l1 = l1 * al1 + ls1;

            #pragma unroll
            for (int nt = 0; nt < 16; nt++) {
                oc[nt][0] *= al0; oc[nt][1] *= al0;
                oc[nt][2] *= al1; oc[nt][3] *= al1;
            }

            #pragma unroll
            for (int ks = 0; ks < 4; ks++) {
                uint32_t pa[4] = { ph[2*ks][0], ph[2*ks][1], ph[2*ks+1][0], ph[2*ks+1][1] };
                const uint32_t va0 = sV + (uint32_t)(((ks * 16 + (lane & 7)
                                   + ((lane >> 3) & 1) * 8) * DP + ((lane >> 4) << 3)) * 2);
                #pragma unroll
                for (int np = 0; np < 8; np++) {
                    uint32_t b0, b1, b2, b3;
                    ldsm_x4t(b0, b1, b2, b3, va0 + np * 32);
                    mma16816h(oc[2 * np],     pa, b0, b1);
                    mma16816h(oc[2 * np + 1], pa, b2, b3);
                }
            }
        }

        if (kt + 1 < nkt)
            asm volatile("cp.async.wait_group 0;" ::: "memory");
        __syncthreads();
    }

    l0 += __shfl_xor_sync(0xffffffffu, l0, 1);
    l0 += __shfl_xor_sync(0xffffffffu, l0, 2);
    l1 += __shfl_xor_sync(0xffffffffu, l1, 1);
    l1 += __shfl_xor_sync(0xffffffffu, l1, 2);

    const float li0 = 1.f / l0, li1 = 1.f / l1;
    const size_t ob0 = ((size_t)b * NT + row0) * NC + h * ND;
    const size_t ob1 = ((size_t)b * NT + row1) * NC + h * ND;
    #pragma unroll
    for (int nt = 0; nt < 16; nt++) {
        int col = nt * 8 + qr * 2;
        *(__half2*)&ao[ob0 + col] = __floats2half2_rn(oc[nt][0] * li0, oc[nt][1] * li0);
        *(__half2*)&ao[ob1 + col] = __floats2half2_rn(oc[nt][2] * li1, oc[nt][3] * li1);
    }
}

// ---------------------------------------------------------------------------
// Launch
// ---------------------------------------------------------------------------
extern "C" void kernel_launch(void* const* d_in, const int* in_sizes, int n_in,
                              void* d_out, int out_size) {
    const float* x      = (const float*)d_in[0];
    const float* rope   = (const float*)d_in[1];
    const float* ln1_w  = (const float*)d_in[2];
    const float* w_qkv  = (const float*)d_in[3];
    const float* qn_w   = (const float*)d_in[4];
    const float* kn_w   = (const float*)d_in[5];
    const float* w_out  = (const float*)d_in[6];
    const float* ln2_w  = (const float*)d_in[7];
    const float* w_fc1  = (const float*)d_in[8];
    const float* w_fc2  = (const float*)d_in[9];
    float* out = (float*)d_out;

    float *qkv, *y1;
    __half *qb, *kb, *vb, *ao, *hb, *xn16, *xnh, *xnl;
    __half *wqT, *woT, *w1T, *w2T;
    cudaGetSymbolAddress((void**)&xnh, g_xn_hi);
    cudaGetSymbolAddress((void**)&xnl, g_xn_lo);
    cudaGetSymbolAddress((void**)&xn16, g_xn16);
    cudaGetSymbolAddress((void**)&qkv, g_qkv);
    cudaGetSymbolAddress((void**)&qb,  g_qb);
    cudaGetSymbolAddress((void**)&kb,  g_kb);
    cudaGetSymbolAddress((void**)&vb,  g_vb);
    cudaGetSymbolAddress((void**)&ao,  g_ao);
    cudaGetSymbolAddress((void**)&y1,  g_y1);
    cudaGetSymbolAddress((void**)&hb,  g_hb);
    cudaGetSymbolAddress((void**)&wqT, g_wqkvT);
    cudaGetSymbolAddress((void**)&woT, g_woutT);
    cudaGetSymbolAddress((void**)&w1T, g_wfc1T);
    cudaGetSymbolAddress((void**)&w2T, g_wfc2T);

    cudaFuncSetAttribute(attn_mma, cudaFuncAttributeMaxDynamicSharedMemorySize, ATT_SMEM2);
    cudaFuncSetAttribute(gemm_a2, cudaFuncAttributeMaxDynamicSharedMemorySize, GEMMA_SMEM);
    cudaFuncSetAttribute(gemm_h1<1>, cudaFuncAttributeMaxDynamicSharedMemorySize, GEMMH_SMEM);
    cudaFuncSetAttribute(gemm_h1<2>, cudaFuncAttributeMaxDynamicSharedMemorySize, GEMMH_SMEM);

    // Weight transpose (all fp16 single)
    wtrans_h<<<dim3(NC3 / 32, NC / 32), 256>>>(w_qkv, wqT, NC, NC3);
    wtrans_h<<<dim3(NC  / 32, NC / 32), 256>>>(w_out, woT, NC, NC);
    wtrans_h<<<dim3(NF  / 32, NC / 32), 256>>>(w_fc1, w1T, NC, NF);
    wtrans_h<<<dim3(NC  / 32, NF / 32), 256>>>(w_fc2, w2T, NF, NC);

    // 1) rmsnorm(x) -> hi/lo fp16
    rmsnorm_split_h<<<NBT, 256>>>(x, ln1_w, xnh, xnl, NC);

    // 2) qkv = xn @ w_qkv (fp32 out), 2-term fp16 (A hi/lo, B single)
    gemm_a2<<<dim3(NC3 / 128, NBT / 128), 256, GEMMA_SMEM>>>(
        xnh, xnl, wqT, qkv, NBT, NC3, NC);

    // 3) RoPE + head rmsnorm + mxfp8 qdq -> fp16 (exact)
    qkv_post<<<NB * NT * NH, 128>>>(qkv, rope, qn_w, kn_w, qb, kb, vb);

    // 4) tensor-core causal attention -> fp16 single
    attn_mma<<<dim3(NT / 128, NB * NH), 256, ATT_SMEM2>>>(qb, kb, vb, ao);

    // 5) y1 = x + attn @ w_out   (1-term fp16)
    gemm_h1<1><<<dim3(NC / 128, NBT / 128), 256, GEMMH_SMEM>>>(
        ao, woT, x, y1, nullptr, NBT, NC, NC);

    // 6) rmsnorm(y1) -> fp16 single
    rmsnorm_h<<<NBT, 256>>>(y1, ln2_w, xn16, NC);

    // 7) h = srelu(xn @ w_fc1) -> fp16 single   (1-term fp16)
    gemm_h1<2><<<dim3(NF / 128, NBT / 128), 256, GEMMH_SMEM>>>(
        xn16, w1T, nullptr, nullptr, hb, NBT, NF, NC);

    // 8) out = y1 + h @ w_fc2   (1-term fp16)
    gemm_h1<1><<<dim3(NC / 128, NBT / 128), 256, GEMMH_SMEM>>>(
        hb, w2T, y1, out, nullptr, NBT, NC, NF);
}